// round 1
// baseline (speedup 1.0000x reference)
#include <cuda_runtime.h>
#include <math.h>

// Problem constants
#define EMB     1024
#define NHEAD   16
#define HDIM    64
#define NBATCH  4
#define SEQ     8192
#define MTOK    (NBATCH * SEQ)          // 32768 tokens

// GEMM tiling
#define BM 128
#define BN 128
#define BK 16
#define TM 8
#define TN 8

// Scratch buffers (device globals: allocation-free per harness rules)
__device__ float g_Q[(size_t)MTOK * EMB];
__device__ float g_K[(size_t)MTOK * EMB];
__device__ float g_V[(size_t)MTOK * EMB];
__device__ float g_Y[(size_t)MTOK * EMB];

// C[m,n] = bias[n] + sum_k A[m,k] * W[n,k]   (A row-major MxK, W row-major NxK)
__global__ __launch_bounds__(256, 2)
void gemm_nt(const float* __restrict__ A, const float* __restrict__ W,
             const float* __restrict__ bias, float* __restrict__ C,
             int M, int N, int K)
{
    __shared__ float As[BK][BM];
    __shared__ float Ws[BK][BN];

    const int tid = threadIdx.x;
    const int tx  = tid & 15;      // N-dir thread coord
    const int ty  = tid >> 4;      // M-dir thread coord

    const float* Ab = A + (size_t)blockIdx.y * BM * K;
    const float* Wb = W + (size_t)blockIdx.x * BN * K;

    // Each thread loads 2 float4 from the A tile and 2 from the W tile per k-slab.
    const int lrow = tid >> 2;           // 0..63
    const int lcol = (tid & 3) << 2;     // 0,4,8,12

    float acc[TM][TN];
    #pragma unroll
    for (int i = 0; i < TM; ++i)
        #pragma unroll
        for (int j = 0; j < TN; ++j) acc[i][j] = 0.0f;

    for (int k0 = 0; k0 < K; k0 += BK) {
        #pragma unroll
        for (int r = 0; r < 2; ++r) {
            int row = lrow + r * 64;
            float4 a = *(const float4*)(Ab + (size_t)row * K + k0 + lcol);
            As[lcol + 0][row] = a.x;
            As[lcol + 1][row] = a.y;
            As[lcol + 2][row] = a.z;
            As[lcol + 3][row] = a.w;
            float4 w = *(const float4*)(Wb + (size_t)row * K + k0 + lcol);
            Ws[lcol + 0][row] = w.x;
            Ws[lcol + 1][row] = w.y;
            Ws[lcol + 2][row] = w.z;
            Ws[lcol + 3][row] = w.w;
        }
        __syncthreads();

        #pragma unroll
        for (int k = 0; k < BK; ++k) {
            float4 a0 = *(const float4*)&As[k][ty * TM];
            float4 a1 = *(const float4*)&As[k][ty * TM + 4];
            float4 w0 = *(const float4*)&Ws[k][tx * TN];
            float4 w1 = *(const float4*)&Ws[k][tx * TN + 4];
            float af[TM] = {a0.x, a0.y, a0.z, a0.w, a1.x, a1.y, a1.z, a1.w};
            float wf[TN] = {w0.x, w0.y, w0.z, w0.w, w1.x, w1.y, w1.z, w1.w};
            #pragma unroll
            for (int i = 0; i < TM; ++i)
                #pragma unroll
                for (int j = 0; j < TN; ++j)
                    acc[i][j] = fmaf(af[i], wf[j], acc[i][j]);
        }
        __syncthreads();
    }

    const int crow0 = blockIdx.y * BM + ty * TM;
    const int ccol0 = blockIdx.x * BN + tx * TN;
    #pragma unroll
    for (int i = 0; i < TM; ++i) {
        float* cp = C + (size_t)(crow0 + i) * N + ccol0;
        #pragma unroll
        for (int j = 0; j < TN; j += 4) {
            float4 v;
            v.x = acc[i][j + 0] + bias[ccol0 + j + 0];
            v.y = acc[i][j + 1] + bias[ccol0 + j + 1];
            v.z = acc[i][j + 2] + bias[ccol0 + j + 2];
            v.w = acc[i][j + 3] + bias[ccol0 + j + 3];
            *(float4*)(cp + j) = v;
        }
    }
}

// Per-token 16x16 head-gram "attention" + scatter reshape into Y.
// One block (256 threads) per token.
__global__ __launch_bounds__(256)
void attn_kernel(const float* __restrict__ Q, const float* __restrict__ K,
                 const float* __restrict__ V, float* __restrict__ Y)
{
    __shared__ float qs[EMB];
    __shared__ float ks[EMB];
    __shared__ float vs[EMB];
    __shared__ float Ash[16][17];

    const int t   = blockIdx.x;          // token id: n*SEQ + s
    const int tid = threadIdx.x;
    const size_t base = (size_t)t * EMB;

    // Load q,k,v rows (1024 floats each = 256 float4; one per thread)
    ((float4*)qs)[tid] = ((const float4*)(Q + base))[tid];
    ((float4*)ks)[tid] = ((const float4*)(K + base))[tid];
    ((float4*)vs)[tid] = ((const float4*)(V + base))[tid];
    __syncthreads();

    // energy[i][j] = (1/sqrt(1024)) * sum_d q[i*64+d]*k[j*64+d]
    const int i = tid >> 4;
    const int j = tid & 15;
    float e = 0.0f;
    #pragma unroll 16
    for (int d = 0; d < HDIM; ++d)
        e = fmaf(qs[i * HDIM + d], ks[j * HDIM + d], e);
    e *= 0.03125f;   // 1/32

    // softmax over j (16-lane groups, aligned within warps)
    float m = e;
    #pragma unroll
    for (int off = 8; off > 0; off >>= 1)
        m = fmaxf(m, __shfl_xor_sync(0xffffffffu, m, off));
    float p = expf(e - m);
    float ssum = p;
    #pragma unroll
    for (int off = 8; off > 0; off >>= 1)
        ssum += __shfl_xor_sync(0xffffffffu, ssum, off);
    Ash[i][j] = p / ssum;
    __syncthreads();

    // O[i][d] = sum_j A[i][j] * v[j*64+d]; thread handles (i2, 4 d's)
    const int i2 = tid >> 4;
    const int dq = tid & 15;       // d quad: d = dq*4 .. dq*4+3
    float4 o = make_float4(0.f, 0.f, 0.f, 0.f);
    #pragma unroll
    for (int jj = 0; jj < 16; ++jj) {
        float a = Ash[i2][jj];
        float4 vv = *(const float4*)(vs + jj * HDIM + dq * 4);
        o.x = fmaf(a, vv.x, o.x);
        o.y = fmaf(a, vv.y, o.y);
        o.z = fmaf(a, vv.z, o.z);
        o.w = fmaf(a, vv.w, o.w);
    }

    // Scatter per the reshape of (N,H,S,D) -> (N,S,E):
    // row = i2*512 + s/16, col = (s%16)*64 + d
    const int n = t >> 13;        // / SEQ
    const int s = t & 8191;       // % SEQ
    const int orow = i2 * 512 + (s >> 4);
    const int ocol = ((s & 15) << 6) + (dq << 2);
    *(float4*)(Y + ((size_t)n * SEQ + orow) * EMB + ocol) = o;
}

extern "C" void kernel_launch(void* const* d_in, const int* in_sizes, int n_in,
                              void* d_out, int out_size)
{
    const float* x  = (const float*)d_in[0];
    const float* Wq = (const float*)d_in[1];
    const float* Wk = (const float*)d_in[2];
    const float* Wv = (const float*)d_in[3];
    const float* Wo = (const float*)d_in[4];
    const float* bq = (const float*)d_in[5];
    const float* bk = (const float*)d_in[6];
    const float* bv = (const float*)d_in[7];
    const float* bo = (const float*)d_in[8];
    float* out = (float*)d_out;

    float *pQ, *pK, *pV, *pY;
    cudaGetSymbolAddress((void**)&pQ, g_Q);
    cudaGetSymbolAddress((void**)&pK, g_K);
    cudaGetSymbolAddress((void**)&pV, g_V);
    cudaGetSymbolAddress((void**)&pY, g_Y);

    dim3 grid(EMB / BN, MTOK / BM);   // (8, 256)
    gemm_nt<<<grid, 256>>>(x, Wq, bq, pQ, MTOK, EMB, EMB);
    gemm_nt<<<grid, 256>>>(x, Wk, bk, pK, MTOK, EMB, EMB);
    gemm_nt<<<grid, 256>>>(x, Wv, bv, pV, MTOK, EMB, EMB);
    attn_kernel<<<MTOK, 256>>>(pQ, pK, pV, pY);
    gemm_nt<<<grid, 256>>>(pY, Wo, bo, out, MTOK, EMB, EMB);
}

// round 3
// speedup vs baseline: 1.7351x; 1.7351x over previous
#include <cuda_runtime.h>
#include <cuda_bf16.h>
#include <math.h>
#include <stdint.h>

#define EMB     1024
#define NHEAD   16
#define HDIM    64
#define NBATCH  4
#define SEQ     8192
#define MTOK    (NBATCH * SEQ)          // 32768

// ---------------- scratch (device globals; allocation-free) ----------------
__device__ float g_Q[(size_t)MTOK * EMB];
__device__ float g_K[(size_t)MTOK * EMB];
__device__ float g_V[(size_t)MTOK * EMB];
__device__ float g_Y[(size_t)MTOK * EMB];
__device__ __nv_bfloat16 g_xhi[(size_t)MTOK * EMB];
__device__ __nv_bfloat16 g_xlo[(size_t)MTOK * EMB];
__device__ __nv_bfloat16 g_yhi[(size_t)MTOK * EMB];
__device__ __nv_bfloat16 g_ylo[(size_t)MTOK * EMB];
__device__ __nv_bfloat16 g_whi[4][(size_t)EMB * EMB];
__device__ __nv_bfloat16 g_wlo[4][(size_t)EMB * EMB];

static __device__ __forceinline__ uint32_t smem_u32(const void* p) {
    uint32_t a;
    asm("{ .reg .u64 t; cvta.to.shared.u64 t, %1; cvt.u32.u64 %0, t; }" : "=r"(a) : "l"(p));
    return a;
}

static __device__ __forceinline__ void ldsm4(uint32_t* r, uint32_t addr) {
    asm volatile("ldmatrix.sync.aligned.m8n8.x4.shared.b16 {%0,%1,%2,%3}, [%4];"
                 : "=r"(r[0]), "=r"(r[1]), "=r"(r[2]), "=r"(r[3]) : "r"(addr));
}

static __device__ __forceinline__ void mma16816(float* d, const uint32_t* a,
                                                uint32_t b0, uint32_t b1) {
    asm volatile(
        "mma.sync.aligned.m16n8k16.row.col.f32.bf16.bf16.f32 "
        "{%0,%1,%2,%3}, {%4,%5,%6,%7}, {%8,%9}, {%0,%1,%2,%3};"
        : "+f"(d[0]), "+f"(d[1]), "+f"(d[2]), "+f"(d[3])
        : "r"(a[0]), "r"(a[1]), "r"(a[2]), "r"(a[3]), "r"(b0), "r"(b1));
}

// ---------------- fp32 -> bf16 hi/lo split ----------------
__global__ __launch_bounds__(256)
void split_fp32(const float* __restrict__ in, __nv_bfloat16* __restrict__ hi,
                __nv_bfloat16* __restrict__ lo, int n4)
{
    int i = blockIdx.x * blockDim.x + threadIdx.x;
    if (i >= n4) return;
    float4 v = ((const float4*)in)[i];
    float f[4] = {v.x, v.y, v.z, v.w};
    __nv_bfloat16 h[4], l[4];
    #pragma unroll
    for (int k = 0; k < 4; ++k) {
        h[k] = __float2bfloat16(f[k]);
        l[k] = __float2bfloat16(f[k] - __bfloat162float(h[k]));
    }
    __nv_bfloat162* hp = (__nv_bfloat162*)hi;
    __nv_bfloat162* lp = (__nv_bfloat162*)lo;
    hp[2 * i + 0] = __nv_bfloat162(h[0], h[1]);
    hp[2 * i + 1] = __nv_bfloat162(h[2], h[3]);
    lp[2 * i + 0] = __nv_bfloat162(l[0], l[1]);
    lp[2 * i + 1] = __nv_bfloat162(l[2], l[3]);
}

// ---------------- HMMA GEMM: C[m,n] = bias[n] + sum_k A[m,k]*W[n,k] ----------------
// bf16 3-term split (Ah*Bh + Ah*Bl + Al*Bh), fp32 accumulate.
// CTA 128x128, 8 warps (2Mx4N), warp 64x32. BK=32. 3-stage cp.async.
// Smem row (per m or n): 128B = [hi: 32 bf16][lo: 32 bf16], XOR-swizzled in 16B chunks.
#define BKG         32
#define NKC         (EMB / BKG)        // 32
#define TILE_B      16384              // 128 rows x 128B
#define STAGE_B     (2 * TILE_B)       // A tile + B tile
#define NSTG        3
#define GEMM_SMEM   (NSTG * STAGE_B)   // 96 KB

__global__ __launch_bounds__(256)
void gemm_mma(const __nv_bfloat16* __restrict__ Ahi, const __nv_bfloat16* __restrict__ Alo,
              const __nv_bfloat16* __restrict__ Bhi, const __nv_bfloat16* __restrict__ Blo,
              const float* __restrict__ bias, float* __restrict__ C)
{
    extern __shared__ __align__(128) char dsm[];
    const uint32_t sbase = smem_u32(dsm);

    const int tid  = threadIdx.x;
    const int wid  = tid >> 5;
    const int lane = tid & 31;
    const int wm   = wid >> 2;          // 0..1
    const int wn   = wid & 3;           // 0..3
    const int bn   = blockIdx.x, bm = blockIdx.y;

    const char* aHi = (const char*)Ahi + (size_t)bm * 128 * 2048;
    const char* aLo = (const char*)Alo + (size_t)bm * 128 * 2048;
    const char* bHi = (const char*)Bhi + (size_t)bn * 128 * 2048;
    const char* bLo = (const char*)Blo + (size_t)bn * 128 * 2048;

    // loader coords: thread handles 4 chunk-ids per matrix per stage
    const int lrow0 = tid >> 3;        // 0..31
    const int lc    = tid & 7;         // chunk 0..7 (0-3 hi, 4-7 lo)
    const char* aSrc = (lc < 4 ? aHi : aLo);
    const char* bSrc = (lc < 4 ? bHi : bLo);
    const int   srcCol = (lc & 3) * 16;

    #define LOAD_STAGE(kc_, slot_) do {                                           \
        uint32_t sb_ = sbase + (slot_) * STAGE_B;                                 \
        _Pragma("unroll")                                                         \
        for (int i_ = 0; i_ < 4; ++i_) {                                          \
            int row_ = lrow0 + i_ * 32;                                           \
            uint32_t dst_ = sb_ + row_ * 128 + ((lc ^ (row_ & 7)) << 4);          \
            const char* sa_ = aSrc + (size_t)row_ * 2048 + (kc_) * 64 + srcCol;   \
            asm volatile("cp.async.cg.shared.global [%0], [%1], 16;"              \
                         :: "r"(dst_), "l"(sa_));                                 \
            const char* sb2_ = bSrc + (size_t)row_ * 2048 + (kc_) * 64 + srcCol;  \
            asm volatile("cp.async.cg.shared.global [%0], [%1], 16;"              \
                         :: "r"(dst_ + TILE_B), "l"(sb2_));                       \
        }                                                                         \
        asm volatile("cp.async.commit_group;");                                   \
    } while (0)

    float acc[4][4][4];
    #pragma unroll
    for (int i = 0; i < 4; ++i)
        #pragma unroll
        for (int j = 0; j < 4; ++j)
            #pragma unroll
            for (int k = 0; k < 4; ++k) acc[i][j][k] = 0.0f;

    LOAD_STAGE(0, 0);
    LOAD_STAGE(1, 1);

    // ldmatrix per-lane invariants
    const int llo = lane & 15;          // row within 16
    const int lhi = lane >> 4;          // k-half chunk select
    const int r7  = llo & 7;
    // row offsets (bytes) for A m-tiles and B n-groups
    uint32_t aRow[4], bRow[2];
    #pragma unroll
    for (int mi = 0; mi < 4; ++mi) aRow[mi] = (wm * 64 + mi * 16 + llo) * 128;
    #pragma unroll
    for (int g = 0; g < 2; ++g)    bRow[g] = TILE_B + (wn * 32 + g * 16 + llo) * 128;

    #define MMA_BLOCK(af_, bf_) do {                                              \
        _Pragma("unroll")                                                         \
        for (int mi_ = 0; mi_ < 4; ++mi_)                                         \
            _Pragma("unroll")                                                     \
            for (int nj_ = 0; nj_ < 4; ++nj_)                                     \
                mma16816(acc[mi_][nj_], (af_)[mi_],                               \
                         (bf_)[nj_ >> 1][nj_ & 1], (bf_)[nj_ >> 1][2 + (nj_ & 1)]); \
    } while (0)

    for (int kc = 0; kc < NKC; ++kc) {
        asm volatile("cp.async.wait_group 1;" ::: "memory");
        __syncthreads();
        if (kc + 2 < NKC) LOAD_STAGE(kc + 2, (kc + 2) % NSTG);

        uint32_t st = sbase + (kc % NSTG) * STAGE_B;
        #pragma unroll
        for (int kh = 0; kh < 2; ++kh) {
            uint32_t af[4][4], bf[2][4];
            const int chH = 2 * kh + lhi;        // hi chunk for this lane
            const int chL = 4 + 2 * kh + lhi;    // lo chunk
            const uint32_t xH = (uint32_t)((chH ^ r7) << 4);
            const uint32_t xL = (uint32_t)((chL ^ r7) << 4);

            #pragma unroll
            for (int mi = 0; mi < 4; ++mi) ldsm4(af[mi], st + aRow[mi] + xH);  // Ah
            #pragma unroll
            for (int g = 0; g < 2; ++g)    ldsm4(bf[g], st + bRow[g] + xH);    // Bh
            MMA_BLOCK(af, bf);                                                  // hh
            #pragma unroll
            for (int g = 0; g < 2; ++g)    ldsm4(bf[g], st + bRow[g] + xL);    // Bl
            MMA_BLOCK(af, bf);                                                  // hl
            #pragma unroll
            for (int mi = 0; mi < 4; ++mi) ldsm4(af[mi], st + aRow[mi] + xL);  // Al
            #pragma unroll
            for (int g = 0; g < 2; ++g)    ldsm4(bf[g], st + bRow[g] + xH);    // Bh again
            MMA_BLOCK(af, bf);                                                  // lh
        }
        __syncthreads();
    }

    // ---- epilogue: direct fp32 stores + bias ----
    const int qr = lane >> 2;           // 0..7
    const int qc = 2 * (lane & 3);      // 0,2,4,6
    #pragma unroll
    for (int nj = 0; nj < 4; ++nj) {
        const int cidx = bn * 128 + wn * 32 + nj * 8 + qc;
        const float2 bv = *(const float2*)&bias[cidx];
        #pragma unroll
        for (int mi = 0; mi < 4; ++mi) {
            const int r = bm * 128 + wm * 64 + mi * 16 + qr;
            float2 v0 = make_float2(acc[mi][nj][0] + bv.x, acc[mi][nj][1] + bv.y);
            float2 v1 = make_float2(acc[mi][nj][2] + bv.x, acc[mi][nj][3] + bv.y);
            *(float2*)&C[(size_t)r * EMB + cidx]       = v0;
            *(float2*)&C[(size_t)(r + 8) * EMB + cidx] = v1;
        }
    }
}

// ---------------- per-token 16x16 head-gram attention + scatter ----------------
__global__ __launch_bounds__(256)
void attn_kernel(const float* __restrict__ Q, const float* __restrict__ K,
                 const float* __restrict__ V, float* __restrict__ Y)
{
    __shared__ float qs[EMB];
    __shared__ float ksT[HDIM][NHEAD + 1];   // transposed: conflict-free over j
    __shared__ float vs[EMB];
    __shared__ float Ash[16][17];

    const int t   = blockIdx.x;
    const int tid = threadIdx.x;
    const size_t base = (size_t)t * EMB;

    ((float4*)qs)[tid] = ((const float4*)(Q + base))[tid];
    float4 kv = ((const float4*)(K + base))[tid];
    {
        int e0 = tid * 4;
        int kj = e0 >> 6;
        int kd = e0 & 63;
        ksT[kd + 0][kj] = kv.x;
        ksT[kd + 1][kj] = kv.y;
        ksT[kd + 2][kj] = kv.z;
        ksT[kd + 3][kj] = kv.w;
    }
    ((float4*)vs)[tid] = ((const float4*)(V + base))[tid];
    __syncthreads();

    const int i = tid >> 4;
    const int j = tid & 15;
    float e = 0.0f;
    #pragma unroll 16
    for (int d = 0; d < HDIM; ++d)
        e = fmaf(qs[i * HDIM + d], ksT[d][j], e);
    e *= 0.03125f;   // 1/sqrt(1024)

    float m = e;
    #pragma unroll
    for (int off = 8; off > 0; off >>= 1)
        m = fmaxf(m, __shfl_xor_sync(0xffffffffu, m, off));
    float p = expf(e - m);
    float ssum = p;
    #pragma unroll
    for (int off = 8; off > 0; off >>= 1)
        ssum += __shfl_xor_sync(0xffffffffu, ssum, off);
    Ash[i][j] = p / ssum;
    __syncthreads();

    const int i2 = tid >> 4;
    const int dq = tid & 15;
    float4 o = make_float4(0.f, 0.f, 0.f, 0.f);
    #pragma unroll
    for (int jj = 0; jj < 16; ++jj) {
        float a = Ash[i2][jj];
        float4 vv = *(const float4*)(vs + jj * HDIM + dq * 4);
        o.x = fmaf(a, vv.x, o.x);
        o.y = fmaf(a, vv.y, o.y);
        o.z = fmaf(a, vv.z, o.z);
        o.w = fmaf(a, vv.w, o.w);
    }

    const int n = t >> 13;
    const int s = t & 8191;
    const int orow = i2 * 512 + (s >> 4);
    const int ocol = ((s & 15) << 6) + (dq << 2);
    *(float4*)(Y + ((size_t)n * SEQ + orow) * EMB + ocol) = o;
}

// ---------------- launch ----------------
extern "C" void kernel_launch(void* const* d_in, const int* in_sizes, int n_in,
                              void* d_out, int out_size)
{
    const float* x  = (const float*)d_in[0];
    const float* W[4] = {(const float*)d_in[1], (const float*)d_in[2],
                         (const float*)d_in[3], (const float*)d_in[4]};
    const float* bq = (const float*)d_in[5];
    const float* bk = (const float*)d_in[6];
    const float* bv = (const float*)d_in[7];
    const float* bo = (const float*)d_in[8];
    float* out = (float*)d_out;

    float *pQ, *pK, *pV, *pY;
    __nv_bfloat16 *xhi, *xlo, *yhi, *ylo, *whi, *wlo;
    cudaGetSymbolAddress((void**)&pQ,  g_Q);
    cudaGetSymbolAddress((void**)&pK,  g_K);
    cudaGetSymbolAddress((void**)&pV,  g_V);
    cudaGetSymbolAddress((void**)&pY,  g_Y);
    cudaGetSymbolAddress((void**)&xhi, g_xhi);
    cudaGetSymbolAddress((void**)&xlo, g_xlo);
    cudaGetSymbolAddress((void**)&yhi, g_yhi);
    cudaGetSymbolAddress((void**)&ylo, g_ylo);
    cudaGetSymbolAddress((void**)&whi, g_whi);
    cudaGetSymbolAddress((void**)&wlo, g_wlo);

    cudaFuncSetAttribute(gemm_mma, cudaFuncAttributeMaxDynamicSharedMemorySize, GEMM_SMEM);

    const int n4x = MTOK * EMB / 4;
    const int n4w = EMB * EMB / 4;

    split_fp32<<<n4x / 256, 256>>>(x, xhi, xlo, n4x);
    for (int i = 0; i < 4; ++i)
        split_fp32<<<n4w / 256, 256>>>(W[i], whi + (size_t)i * EMB * EMB,
                                       wlo + (size_t)i * EMB * EMB, n4w);

    dim3 grid(EMB / 128, MTOK / 128);   // (8, 256)
    gemm_mma<<<grid, 256, GEMM_SMEM>>>(xhi, xlo, whi + 0 * (size_t)EMB * EMB,
                                       wlo + 0 * (size_t)EMB * EMB, bq, pQ);
    gemm_mma<<<grid, 256, GEMM_SMEM>>>(xhi, xlo, whi + 1 * (size_t)EMB * EMB,
                                       wlo + 1 * (size_t)EMB * EMB, bk, pK);
    gemm_mma<<<grid, 256, GEMM_SMEM>>>(xhi, xlo, whi + 2 * (size_t)EMB * EMB,
                                       wlo + 2 * (size_t)EMB * EMB, bv, pV);

    attn_kernel<<<MTOK, 256>>>(pQ, pK, pV, pY);

    split_fp32<<<n4x / 256, 256>>>(pY, yhi, ylo, n4x);
    gemm_mma<<<grid, 256, GEMM_SMEM>>>(yhi, ylo, whi + 3 * (size_t)EMB * EMB,
                                       wlo + 3 * (size_t)EMB * EMB, bo, out);
}

// round 4
// speedup vs baseline: 2.7392x; 1.5787x over previous
#include <cuda_runtime.h>
#include <cuda_bf16.h>
#include <math.h>
#include <stdint.h>

#define EMB     1024
#define NHEAD   16
#define HDIM    64
#define NBATCH  4
#define SEQ     8192
#define MTOK    (NBATCH * SEQ)          // 32768

// ---------------- scratch (device globals; allocation-free) ----------------
__device__ float g_Q[(size_t)MTOK * EMB];
__device__ float g_K[(size_t)MTOK * EMB];
__device__ float g_V[(size_t)MTOK * EMB];
__device__ __nv_bfloat16 g_xhi[(size_t)MTOK * EMB];
__device__ __nv_bfloat16 g_xlo[(size_t)MTOK * EMB];
__device__ __nv_bfloat16 g_yhi[(size_t)MTOK * EMB];
__device__ __nv_bfloat16 g_ylo[(size_t)MTOK * EMB];
__device__ __nv_bfloat16 g_whi[4][(size_t)EMB * EMB];
__device__ __nv_bfloat16 g_wlo[4][(size_t)EMB * EMB];

static __device__ __forceinline__ uint32_t smem_u32(const void* p) {
    uint32_t a;
    asm("{ .reg .u64 t; cvta.to.shared.u64 t, %1; cvt.u32.u64 %0, t; }" : "=r"(a) : "l"(p));
    return a;
}

static __device__ __forceinline__ void ldsm4(uint32_t* r, uint32_t addr) {
    asm volatile("ldmatrix.sync.aligned.m8n8.x4.shared.b16 {%0,%1,%2,%3}, [%4];"
                 : "=r"(r[0]), "=r"(r[1]), "=r"(r[2]), "=r"(r[3]) : "r"(addr));
}

static __device__ __forceinline__ void mma16816(float* d, const uint32_t* a,
                                                uint32_t b0, uint32_t b1) {
    asm volatile(
        "mma.sync.aligned.m16n8k16.row.col.f32.bf16.bf16.f32 "
        "{%0,%1,%2,%3}, {%4,%5,%6,%7}, {%8,%9}, {%0,%1,%2,%3};"
        : "+f"(d[0]), "+f"(d[1]), "+f"(d[2]), "+f"(d[3])
        : "r"(a[0]), "r"(a[1]), "r"(a[2]), "r"(a[3]), "r"(b0), "r"(b1));
}

// ---------------- fp32 -> bf16 hi/lo split ----------------
__global__ __launch_bounds__(256)
void split_fp32(const float* __restrict__ in, __nv_bfloat16* __restrict__ hi,
                __nv_bfloat16* __restrict__ lo, int n4)
{
    int i = blockIdx.x * blockDim.x + threadIdx.x;
    if (i >= n4) return;
    float4 v = ((const float4*)in)[i];
    float f[4] = {v.x, v.y, v.z, v.w};
    __nv_bfloat16 h[4], l[4];
    #pragma unroll
    for (int k = 0; k < 4; ++k) {
        h[k] = __float2bfloat16(f[k]);
        l[k] = __float2bfloat16(f[k] - __bfloat162float(h[k]));
    }
    __nv_bfloat162* hp = (__nv_bfloat162*)hi;
    __nv_bfloat162* lp = (__nv_bfloat162*)lo;
    hp[2 * i + 0] = __nv_bfloat162(h[0], h[1]);
    hp[2 * i + 1] = __nv_bfloat162(h[2], h[3]);
    lp[2 * i + 0] = __nv_bfloat162(l[0], l[1]);
    lp[2 * i + 1] = __nv_bfloat162(l[2], l[3]);
}

// ---------------- HMMA GEMM: C[m,n] = bias[n] + sum_k A[m,k]*W[n,k] ----------------
// bf16 3-term split (Ah*Bh + Ah*Bl + Al*Bh), fp32 accumulate.
// CTA 128x128, 8 warps (2Mx4N), warp 64x32. BK=32. 3-stage cp.async.
// Smem row (per m or n): 128B = [hi: 32 bf16][lo: 32 bf16], XOR-swizzled in 16B chunks.
#define BKG         32
#define NKC         (EMB / BKG)        // 32
#define TILE_B      16384              // 128 rows x 128B
#define STAGE_B     (2 * TILE_B)       // A tile + B tile
#define NSTG        3
#define GEMM_SMEM   (NSTG * STAGE_B)   // 96 KB

__global__ __launch_bounds__(256, 2)
void gemm_mma(const __nv_bfloat16* __restrict__ Ahi, const __nv_bfloat16* __restrict__ Alo,
              const __nv_bfloat16* __restrict__ Bhi, const __nv_bfloat16* __restrict__ Blo,
              const float* __restrict__ bias, float* __restrict__ C)
{
    extern __shared__ __align__(128) char dsm[];
    const uint32_t sbase = smem_u32(dsm);

    const int tid  = threadIdx.x;
    const int wid  = tid >> 5;
    const int lane = tid & 31;
    const int wm   = wid >> 2;          // 0..1
    const int wn   = wid & 3;           // 0..3
    const int bn   = blockIdx.x, bm = blockIdx.y;

    const char* aHi = (const char*)Ahi + (size_t)bm * 128 * 2048;
    const char* aLo = (const char*)Alo + (size_t)bm * 128 * 2048;
    const char* bHi = (const char*)Bhi + (size_t)bn * 128 * 2048;
    const char* bLo = (const char*)Blo + (size_t)bn * 128 * 2048;

    // loader coords: thread handles 4 chunk-ids per matrix per stage
    const int lrow0 = tid >> 3;        // 0..31
    const int lc    = tid & 7;         // chunk 0..7 (0-3 hi, 4-7 lo)
    const char* aSrc = (lc < 4 ? aHi : aLo);
    const char* bSrc = (lc < 4 ? bHi : bLo);
    const int   srcCol = (lc & 3) * 16;

    #define LOAD_STAGE(kc_, slot_) do {                                           \
        uint32_t sb_ = sbase + (slot_) * STAGE_B;                                 \
        _Pragma("unroll")                                                         \
        for (int i_ = 0; i_ < 4; ++i_) {                                          \
            int row_ = lrow0 + i_ * 32;                                           \
            uint32_t dst_ = sb_ + row_ * 128 + ((lc ^ (row_ & 7)) << 4);          \
            const char* sa_ = aSrc + (size_t)row_ * 2048 + (kc_) * 64 + srcCol;   \
            asm volatile("cp.async.cg.shared.global [%0], [%1], 16;"              \
                         :: "r"(dst_), "l"(sa_));                                 \
            const char* sb2_ = bSrc + (size_t)row_ * 2048 + (kc_) * 64 + srcCol;  \
            asm volatile("cp.async.cg.shared.global [%0], [%1], 16;"              \
                         :: "r"(dst_ + TILE_B), "l"(sb2_));                       \
        }                                                                         \
        asm volatile("cp.async.commit_group;");                                   \
    } while (0)

    float acc[4][4][4];
    #pragma unroll
    for (int i = 0; i < 4; ++i)
        #pragma unroll
        for (int j = 0; j < 4; ++j)
            #pragma unroll
            for (int k = 0; k < 4; ++k) acc[i][j][k] = 0.0f;

    LOAD_STAGE(0, 0);
    LOAD_STAGE(1, 1);

    // ldmatrix per-lane invariants
    const int llo = lane & 15;          // row within 16
    const int lhi = lane >> 4;          // k-half chunk select
    const int r7  = llo & 7;
    uint32_t aRow[4], bRow[2];
    #pragma unroll
    for (int mi = 0; mi < 4; ++mi) aRow[mi] = (wm * 64 + mi * 16 + llo) * 128;
    #pragma unroll
    for (int g = 0; g < 2; ++g)    bRow[g] = TILE_B + (wn * 32 + g * 16 + llo) * 128;

    #define MMA_BLOCK(af_, bf_) do {                                              \
        _Pragma("unroll")                                                         \
        for (int mi_ = 0; mi_ < 4; ++mi_)                                         \
            _Pragma("unroll")                                                     \
            for (int nj_ = 0; nj_ < 4; ++nj_)                                     \
                mma16816(acc[mi_][nj_], (af_)[mi_],                               \
                         (bf_)[nj_ >> 1][nj_ & 1], (bf_)[nj_ >> 1][2 + (nj_ & 1)]); \
    } while (0)

    for (int kc = 0; kc < NKC; ++kc) {
        asm volatile("cp.async.wait_group 1;" ::: "memory");
        __syncthreads();                       // single sync per iteration:
        // reads of slot kc%3 at iter kc happen-before this sync at iter kc+1,
        // which precedes the overwrite of that slot.
        if (kc + 2 < NKC) LOAD_STAGE(kc + 2, (kc + 2) % NSTG);
        else              asm volatile("cp.async.commit_group;");   // keep stage kc covered by wait 1

        uint32_t st = sbase + (kc % NSTG) * STAGE_B;
        #pragma unroll
        for (int kh = 0; kh < 2; ++kh) {
            uint32_t af[4][4], bfH[2][4], bfL[2][4];
            const int chH = 2 * kh + lhi;        // hi chunk for this lane
            const int chL = 4 + 2 * kh + lhi;    // lo chunk
            const uint32_t xH = (uint32_t)((chH ^ r7) << 4);
            const uint32_t xL = (uint32_t)((chL ^ r7) << 4);

            // front-load 8 ldsm for MLP, then compute; afL reuses af regs after hl
            #pragma unroll
            for (int mi = 0; mi < 4; ++mi) ldsm4(af[mi], st + aRow[mi] + xH);  // Ah
            #pragma unroll
            for (int g = 0; g < 2; ++g)    ldsm4(bfH[g], st + bRow[g] + xH);   // Bh
            #pragma unroll
            for (int g = 0; g < 2; ++g)    ldsm4(bfL[g], st + bRow[g] + xL);   // Bl
            MMA_BLOCK(af, bfH);                                                 // hh
            MMA_BLOCK(af, bfL);                                                 // hl
            #pragma unroll
            for (int mi = 0; mi < 4; ++mi) ldsm4(af[mi], st + aRow[mi] + xL);  // Al
            MMA_BLOCK(af, bfH);                                                 // lh
        }
    }

    // ---- epilogue: direct fp32 stores + bias ----
    const int qr = lane >> 2;           // 0..7
    const int qc = 2 * (lane & 3);      // 0,2,4,6
    #pragma unroll
    for (int nj = 0; nj < 4; ++nj) {
        const int cidx = bn * 128 + wn * 32 + nj * 8 + qc;
        const float2 bv = *(const float2*)&bias[cidx];
        #pragma unroll
        for (int mi = 0; mi < 4; ++mi) {
            const int r = bm * 128 + wm * 64 + mi * 16 + qr;
            float2 v0 = make_float2(acc[mi][nj][0] + bv.x, acc[mi][nj][1] + bv.y);
            float2 v1 = make_float2(acc[mi][nj][2] + bv.x, acc[mi][nj][3] + bv.y);
            *(float2*)&C[(size_t)r * EMB + cidx]       = v0;
            *(float2*)&C[(size_t)(r + 8) * EMB + cidx] = v1;
        }
    }
}

// ---------------- per-token 16x16 head-gram attention + scatter ----------------
// Writes bf16 hi/lo split of Y directly (fused with the former split kernel).
__global__ __launch_bounds__(256)
void attn_kernel(const float* __restrict__ Q, const float* __restrict__ K,
                 const float* __restrict__ V, __nv_bfloat16* __restrict__ Yhi,
                 __nv_bfloat16* __restrict__ Ylo)
{
    __shared__ float qs[EMB];
    __shared__ float ksT[HDIM][NHEAD + 1];   // transposed: conflict-free over j
    __shared__ float vs[EMB];
    __shared__ float Ash[16][17];

    const int t   = blockIdx.x;
    const int tid = threadIdx.x;
    const size_t base = (size_t)t * EMB;

    ((float4*)qs)[tid] = ((const float4*)(Q + base))[tid];
    float4 kv = ((const float4*)(K + base))[tid];
    {
        int e0 = tid * 4;
        int kj = e0 >> 6;
        int kd = e0 & 63;
        ksT[kd + 0][kj] = kv.x;
        ksT[kd + 1][kj] = kv.y;
        ksT[kd + 2][kj] = kv.z;
        ksT[kd + 3][kj] = kv.w;
    }
    ((float4*)vs)[tid] = ((const float4*)(V + base))[tid];
    __syncthreads();

    const int i = tid >> 4;
    const int j = tid & 15;
    float e = 0.0f;
    #pragma unroll 16
    for (int d = 0; d < HDIM; ++d)
        e = fmaf(qs[i * HDIM + d], ksT[d][j], e);
    e *= 0.03125f;   // 1/sqrt(1024)

    float m = e;
    #pragma unroll
    for (int off = 8; off > 0; off >>= 1)
        m = fmaxf(m, __shfl_xor_sync(0xffffffffu, m, off));
    float p = expf(e - m);
    float ssum = p;
    #pragma unroll
    for (int off = 8; off > 0; off >>= 1)
        ssum += __shfl_xor_sync(0xffffffffu, ssum, off);
    Ash[i][j] = p / ssum;
    __syncthreads();

    const int i2 = tid >> 4;
    const int dq = tid & 15;
    float4 o = make_float4(0.f, 0.f, 0.f, 0.f);
    #pragma unroll
    for (int jj = 0; jj < 16; ++jj) {
        float a = Ash[i2][jj];
        float4 vv = *(const float4*)(vs + jj * HDIM + dq * 4);
        o.x = fmaf(a, vv.x, o.x);
        o.y = fmaf(a, vv.y, o.y);
        o.z = fmaf(a, vv.z, o.z);
        o.w = fmaf(a, vv.w, o.w);
    }

    const int n = t >> 13;
    const int s = t & 8191;
    const int orow = i2 * 512 + (s >> 4);
    const int ocol = ((s & 15) << 6) + (dq << 2);
    const size_t off = ((size_t)n * SEQ + orow) * EMB + ocol;

    float f[4] = {o.x, o.y, o.z, o.w};
    __nv_bfloat16 h[4], l[4];
    #pragma unroll
    for (int k = 0; k < 4; ++k) {
        h[k] = __float2bfloat16(f[k]);
        l[k] = __float2bfloat16(f[k] - __bfloat162float(h[k]));
    }
    __nv_bfloat162 h01, h23, l01, l23;
    h01.x = h[0]; h01.y = h[1]; h23.x = h[2]; h23.y = h[3];
    l01.x = l[0]; l01.y = l[1]; l23.x = l[2]; l23.y = l[3];
    uint2 hv = make_uint2(*(uint32_t*)&h01, *(uint32_t*)&h23);
    uint2 lv = make_uint2(*(uint32_t*)&l01, *(uint32_t*)&l23);
    *(uint2*)(Yhi + off) = hv;
    *(uint2*)(Ylo + off) = lv;
}

// ---------------- launch ----------------
extern "C" void kernel_launch(void* const* d_in, const int* in_sizes, int n_in,
                              void* d_out, int out_size)
{
    const float* x  = (const float*)d_in[0];
    const float* W[4] = {(const float*)d_in[1], (const float*)d_in[2],
                         (const float*)d_in[3], (const float*)d_in[4]};
    const float* bq = (const float*)d_in[5];
    const float* bk = (const float*)d_in[6];
    const float* bv = (const float*)d_in[7];
    const float* bo = (const float*)d_in[8];
    float* out = (float*)d_out;

    float *pQ, *pK, *pV;
    __nv_bfloat16 *xhi, *xlo, *yhi, *ylo, *whi, *wlo;
    cudaGetSymbolAddress((void**)&pQ,  g_Q);
    cudaGetSymbolAddress((void**)&pK,  g_K);
    cudaGetSymbolAddress((void**)&pV,  g_V);
    cudaGetSymbolAddress((void**)&xhi, g_xhi);
    cudaGetSymbolAddress((void**)&xlo, g_xlo);
    cudaGetSymbolAddress((void**)&yhi, g_yhi);
    cudaGetSymbolAddress((void**)&ylo, g_ylo);
    cudaGetSymbolAddress((void**)&whi, g_whi);
    cudaGetSymbolAddress((void**)&wlo, g_wlo);

    cudaFuncSetAttribute(gemm_mma, cudaFuncAttributeMaxDynamicSharedMemorySize, GEMM_SMEM);

    const int n4x = MTOK * EMB / 4;
    const int n4w = EMB * EMB / 4;

    split_fp32<<<n4x / 256, 256>>>(x, xhi, xlo, n4x);
    for (int i = 0; i < 4; ++i)
        split_fp32<<<n4w / 256, 256>>>(W[i], whi + (size_t)i * EMB * EMB,
                                       wlo + (size_t)i * EMB * EMB, n4w);

    dim3 grid(EMB / 128, MTOK / 128);   // (8, 256)
    gemm_mma<<<grid, 256, GEMM_SMEM>>>(xhi, xlo, whi + 0 * (size_t)EMB * EMB,
                                       wlo + 0 * (size_t)EMB * EMB, bq, pQ);
    gemm_mma<<<grid, 256, GEMM_SMEM>>>(xhi, xlo, whi + 1 * (size_t)EMB * EMB,
                                       wlo + 1 * (size_t)EMB * EMB, bk, pK);
    gemm_mma<<<grid, 256, GEMM_SMEM>>>(xhi, xlo, whi + 2 * (size_t)EMB * EMB,
                                       wlo + 2 * (size_t)EMB * EMB, bv, pV);

    attn_kernel<<<MTOK, 256>>>(pQ, pK, pV, yhi, ylo);

    gemm_mma<<<grid, 256, GEMM_SMEM>>>(yhi, ylo, whi + 3 * (size_t)EMB * EMB,
                                       wlo + 3 * (size_t)EMB * EMB, bo, out);
}